// round 15
// baseline (speedup 1.0000x reference)
#include <cuda_runtime.h>
#include <cuda_fp16.h>

#define BB    8
#define PP    16384
#define KN    16
#define CK    144
#define IMG   (16*128*128)    // 262144 = 2^18
#define NT    256
#define NPX   2
#define WKSTR  148                        // k-row stride (floats); 20*kp mod 32 deg-1
#define WPXSTR (KN*WKSTR)                 // 2368 floats (0 mod 32; cpx via Delta=18 window)
#define PPXB   (CK*16)                    // 2304 B patch px stride (16B fp16 rows)

#define WFL        (NPX*WPXSTR)           // 4736 floats
#define WBYTES     (NPX*KN*CK*4)          // 18432
#define SMEM_BYTES (WFL*4 + NPX*PPXB + 8) // 23560

// 4 MB scratch: x transposed + fp16-packed, batch-innermost (row = 16B)
__device__ __align__(16) __half g_xth[IMG * BB];
__device__ int g_idx_is64;

__device__ __forceinline__ void fma2(unsigned long long& d,
                                     unsigned long long a, unsigned long long b) {
    asm("fma.rn.f32x2 %0, %1, %2, %0;" : "+l"(d) : "l"(a), "l"(b));
}

// Transpose+pack x [B][IMG] -> g_xth [IMG][B]; block 0 probes idx dtype.
__global__ __launch_bounds__(256) void transpose_kernel(
    const float* __restrict__ x, const unsigned* __restrict__ h32)
{
    if (blockIdx.x == 0 && threadIdx.x < 32) {
        unsigned v = h32[2u * (threadIdx.x * 36000u) + 1u];
        int all0 = __all_sync(0xFFFFFFFFu, v == 0u);
        if (threadIdx.x == 0) g_idx_is64 = all0;
    }
    int i = blockIdx.x * 256 + threadIdx.x;
    __half2 h[4];
    #pragma unroll
    for (int q = 0; q < 4; q++) {
        float lo = __ldg(&x[(2 * q) * IMG + i]);
        float hi = __ldg(&x[(2 * q + 1) * IMG + i]);
        h[q] = __floats2half2_rn(lo, hi);
    }
    *(uint4*)&g_xth[(size_t)i * BB] = *(uint4*)h;
}

__global__ __launch_bounds__(NT, 6) void abc2d_kernel(
    const float* __restrict__ weights,
    const unsigned* __restrict__ hidx32,
    float* __restrict__ out)
{
    extern __shared__ __align__(16) float smem[];
    float*  wsm   = smem;                               // [px][16][WKSTR]
    __half* patch = (__half*)((char*)smem + WFL * 4);   // [px][c][8]
    unsigned mbar = (unsigned)__cvta_generic_to_shared((char*)smem + WFL * 4 + NPX * PPXB);

    const int p0 = blockIdx.x * NPX;
    const int t  = threadIdx.x;
    const int is64 = g_idx_is64;

    if (t == 0) {
        asm volatile("mbarrier.init.shared.b64 [%0], 1;" :: "r"(mbar) : "memory");
        asm volatile("mbarrier.arrive.expect_tx.shared.b64 _, [%0], %1;"
                     :: "r"(mbar), "r"(WBYTES) : "memory");
    }
    __syncthreads();

    // ---- weights: 32 per-k-row bulk copies (576 B) into padded rows ----
    if (t < 32) {
        int px = t >> 4, k = t & 15;
        unsigned d = (unsigned)__cvta_generic_to_shared(wsm + px * WPXSTR + k * WKSTR);
        const float* src = weights + (size_t)(p0 + px) * (KN * CK) + k * CK;
        asm volatile(
            "{\n\t"
            ".reg .b64 pol;\n\t"
            "createpolicy.fractional.L2::evict_first.b64 pol, 1.0;\n\t"
            "cp.async.bulk.shared::cluster.global.mbarrier::complete_tx::bytes.L2::cache_hint"
            " [%0], [%1], %2, [%3], pol;\n\t"
            "}\n"
            :: "r"(d), "l"(src), "r"(CK * 4), "r"(mbar) : "memory");
    }

    // ---- gather (overlaps copies): 144 pair-tasks; paired idx, 2 LDG.128 each ----
    if (t < NPX * CK / 2) {                             // 144 tasks
        int px = t / (CK / 2);
        int c0 = (t - px * (CK / 2)) * 2;
        int elem = (p0 + px) * CK + c0;                 // even -> aligned vec loads
        unsigned i0, i1;
        if (is64) {
            uint4 v = __ldcs((const uint4*)&hidx32[2 * elem]);
            i0 = v.x; i1 = v.z;
        } else {
            uint2 v = __ldcs((const uint2*)&hidx32[elem]);
            i0 = v.x; i1 = v.y;
        }
        uint4 v0 = __ldg((const uint4*)&g_xth[(size_t)(i0 & (IMG - 1)) * BB]);
        uint4 v1 = __ldg((const uint4*)&g_xth[(size_t)(i1 & (IMG - 1)) * BB]);
        char* pb = (char*)patch + px * PPXB;
        *(uint4*)(pb + c0 * 16)      = v0;
        *(uint4*)(pb + c0 * 16 + 16) = v1;
    }

    __syncthreads();          // patch visible

    // wait for weight copies
    asm volatile(
        "{\n\t"
        ".reg .pred P1;\n\t"
        "WL_%=:\n\t"
        "mbarrier.try_wait.parity.acquire.cta.shared::cta.b64 P1, [%0], 0, 0x989680;\n\t"
        "@P1 bra.uni WD_%=;\n\t"
        "bra.uni WL_%=;\n\t"
        "WD_%=:\n\t"
        "}\n"
        :: "r"(mbar) : "memory");

    // ---- compute: thread = (kp, cpx, s in 16); k-rows (kp, kp+8); 9-c window
    //      cb = 9s + 18*cpx (mod 144): lane banks = full 32-perm, praw 1-phase.
    const int kp  = t & 7;
    const int cpx = (t >> 3) & 1;
    const int s   = t >> 4;
    int cb = s * 9 + cpx * 18;
    if (cb >= CK) cb -= CK;
    float rr0[8], rr1[8];
    {
        const float* wr = wsm + cpx * WPXSTR + kp * WKSTR;
        const char*  pb = (const char*)patch + cpx * PPXB;
        unsigned long long a0[4] = {0ull,0ull,0ull,0ull};
        unsigned long long a1[4] = {0ull,0ull,0ull,0ull};
        #pragma unroll
        for (int j = 0; j < 9; j++) {
            int c = cb + j;
            if (c >= CK) c -= CK;
            uint4 praw = *(const uint4*)(pb + c * 16);   // 8 halves, row broadcast
            const __half2* ph = (const __half2*)&praw;
            float2 f0 = __half22float2(ph[0]);
            float2 f1 = __half22float2(ph[1]);
            float2 f2 = __half22float2(ph[2]);
            float2 f3 = __half22float2(ph[3]);
            unsigned long long pf0 = *(unsigned long long*)&f0;
            unsigned long long pf1 = *(unsigned long long*)&f1;
            unsigned long long pf2 = *(unsigned long long*)&f2;
            unsigned long long pf3 = *(unsigned long long*)&f3;
            float w0 = wr[c];
            float w1 = wr[8 * WKSTR + c];
            unsigned long long W0, W1;
            asm("mov.b64 %0, {%1, %1};" : "=l"(W0) : "f"(w0));
            asm("mov.b64 %0, {%1, %1};" : "=l"(W1) : "f"(w1));
            fma2(a0[0], W0, pf0); fma2(a0[1], W0, pf1);
            fma2(a0[2], W0, pf2); fma2(a0[3], W0, pf3);
            fma2(a1[0], W1, pf0); fma2(a1[1], W1, pf1);
            fma2(a1[2], W1, pf2); fma2(a1[3], W1, pf3);
        }
        #pragma unroll
        for (int q = 0; q < 4; q++) {
            rr0[2 * q]     = __uint_as_float((unsigned)a0[q]);
            rr0[2 * q + 1] = __uint_as_float((unsigned)(a0[q] >> 32));
            rr1[2 * q]     = __uint_as_float((unsigned)a1[q]);
            rr1[2 * q + 1] = __uint_as_float((unsigned)(a1[q] >> 32));
        }
    }
    // reduce s-parity (lane bit 4)
    #pragma unroll
    for (int b = 0; b < 8; b++) {
        rr0[b] += __shfl_xor_sync(0xFFFFFFFFu, rr0[b], 16);
        rr1[b] += __shfl_xor_sync(0xFFFFFFFFu, rr1[b], 16);
    }

    // ---- stage 8 warp-partials: outsm[(w*2+cpx)*8+b][16] at slot kp*2+half ----
    __syncthreads();                        // all smem reads done; overlay
    float* outsm = smem;                    // 8*2*8*16 = 2048 floats
    if ((t & 16) == 0) {
        const int w = t >> 5;
        float* dst = outsm + ((w * 2 + cpx) * 8) * KN + kp * 2;
        #pragma unroll
        for (int b = 0; b < 8; b++)
            *(float2*)&dst[b * KN] = make_float2(rr0[b], rr1[b]);
    }
    __syncthreads();

    if (t < KN * BB) {
        const int k = t & 15, b = t >> 4;
        const int ki = (k & 7) * 2 + (k >> 3);      // slot for k in (kp, kp+8) pairing
        float s0 = 0.f, s1 = 0.f;
        #pragma unroll
        for (int w = 0; w < 8; w++) {
            s0 += outsm[((w * 2 + 0) * 8 + b) * KN + ki];
            s1 += outsm[((w * 2 + 1) * 8 + b) * KN + ki];
        }
        __stcs((float2*)&out[(((size_t)b * KN + k) << 14) + p0], make_float2(s0, s1));
    }
}

extern "C" void kernel_launch(void* const* d_in, const int* in_sizes, int n_in,
                              void* d_out, int out_size) {
    const float*    x   = (const float*)d_in[0];
    const float*    w   = (const float*)d_in[1];
    const unsigned* hid = (const unsigned*)d_in[2];
    float*          out = (float*)d_out;
    (void)in_sizes; (void)n_in; (void)out_size;

    cudaFuncSetAttribute(abc2d_kernel,
                         cudaFuncAttributeMaxDynamicSharedMemorySize, SMEM_BYTES);
    transpose_kernel<<<IMG / 256, 256>>>(x, hid);
    abc2d_kernel<<<PP / NPX, NT, SMEM_BYTES>>>(w, hid, out);
}